// round 1
// baseline (speedup 1.0000x reference)
#include <cuda_runtime.h>
#include <cuda_bf16.h>

// Erosion2d: out[n,c,y,x] = min over 3x3 window (pad 1e9) of x[n,c,...]
// Shape: (16, 64, 256, 256) fp32. Memory-bound: 512 MB total traffic.
//
// Strategy: separable min. One warp owns a 64-row strip of one 256x256 image.
// Each lane holds 8 pixels/row as two float4s (contiguous-16B layout so every
// LDG.128 / STG.128 is a fully coalesced 512B warp transaction). Horizontal
// 3-min uses 6 warp shuffles; vertical 3-min uses a rolling 3-row register
// pipeline so every input row is read exactly once.

#define EH 256
#define EW 256
#define STRIPS 4
#define ROWS_PER_STRIP (EH / STRIPS)

struct Row8 { float4 a, b; };

__device__ __forceinline__ float fmin3(float a, float b, float c) {
    return fminf(a, fminf(b, c));
}

__device__ __forceinline__ Row8 load_row(const float* __restrict__ src, int y,
                                         int o0, int o1) {
    Row8 r;
    if ((unsigned)y < (unsigned)EH) {
        const float* p = src + (size_t)y * EW;
        r.a = *reinterpret_cast<const float4*>(p + o0);
        r.b = *reinterpret_cast<const float4*>(p + o1);
    } else {
        const float inf = __int_as_float(0x7f800000);
        r.a = make_float4(inf, inf, inf, inf);
        r.b = r.a;
    }
    return r;
}

// Horizontal 3-tap min. Lane l holds x = [4l, 4l+4) in .a and
// x = [128+4l, 128+4l+4) in .b. Neighbors across lanes via shuffle.
__device__ __forceinline__ Row8 hmin_row(Row8 v, int lane) {
    const unsigned FULL = 0xffffffffu;
    const float inf = __int_as_float(0x7f800000);

    float lA   = __shfl_up_sync  (FULL, v.a.w, 1);  // x = 4l-1
    float rA   = __shfl_down_sync(FULL, v.a.x, 1);  // x = 4l+4
    float bx0  = __shfl_sync     (FULL, v.b.x, 0);  // x = 128 (for lane 31's rA)
    float aw31 = __shfl_sync     (FULL, v.a.w, 31); // x = 127 (for lane 0's lB)
    float lB   = __shfl_up_sync  (FULL, v.b.w, 1);  // x = 128+4l-1
    float rB   = __shfl_down_sync(FULL, v.b.x, 1);  // x = 128+4l+4

    if (lane == 0)  { lA = inf;  lB = aw31; }  // x=-1 is padding
    if (lane == 31) { rA = bx0;  rB = inf;  }  // x=256 is padding

    Row8 h;
    h.a.x = fmin3(lA,    v.a.x, v.a.y);
    h.a.y = fmin3(v.a.x, v.a.y, v.a.z);
    h.a.z = fmin3(v.a.y, v.a.z, v.a.w);
    h.a.w = fmin3(v.a.z, v.a.w, rA);
    h.b.x = fmin3(lB,    v.b.x, v.b.y);
    h.b.y = fmin3(v.b.x, v.b.y, v.b.z);
    h.b.z = fmin3(v.b.y, v.b.z, v.b.w);
    h.b.w = fmin3(v.b.z, v.b.w, rB);
    return h;
}

__device__ __forceinline__ Row8 vmin3(Row8 p, Row8 q, Row8 r) {
    Row8 o;
    o.a.x = fmin3(p.a.x, q.a.x, r.a.x);
    o.a.y = fmin3(p.a.y, q.a.y, r.a.y);
    o.a.z = fmin3(p.a.z, q.a.z, r.a.z);
    o.a.w = fmin3(p.a.w, q.a.w, r.a.w);
    o.b.x = fmin3(p.b.x, q.b.x, r.b.x);
    o.b.y = fmin3(p.b.y, q.b.y, r.b.y);
    o.b.z = fmin3(p.b.z, q.b.z, r.b.z);
    o.b.w = fmin3(p.b.w, q.b.w, r.b.w);
    return o;
}

__global__ __launch_bounds__(256)
void Erosion2d_86517821212128_kernel(const float* __restrict__ x,
                                     float* __restrict__ out,
                                     int n_imgs) {
    const int gw    = (int)((blockIdx.x * blockDim.x + threadIdx.x) >> 5);
    const int lane  = (int)(threadIdx.x & 31);
    const int img   = gw / STRIPS;
    const int strip = gw - img * STRIPS;
    if (img >= n_imgs) return;

    const float* src = x   + (size_t)img * (EH * EW);
    float*       dst = out + (size_t)img * (EH * EW);

    const int o0 = lane * 4;         // first half-row, x in [0,128)
    const int o1 = 128 + lane * 4;   // second half-row, x in [128,256)

    const int ys = strip * ROWS_PER_STRIP;

    // Rolling pipeline: hA = hmin(row yo-1), hB = hmin(row yo)
    Row8 hA = hmin_row(load_row(src, ys - 1, o0, o1), lane);
    Row8 hB = hmin_row(load_row(src, ys,     o0, o1), lane);

#pragma unroll 4
    for (int yo = ys; yo < ys + ROWS_PER_STRIP; ++yo) {
        Row8 hC = hmin_row(load_row(src, yo + 1, o0, o1), lane);
        Row8 o  = vmin3(hA, hB, hC);
        float* p = dst + (size_t)yo * EW;
        *reinterpret_cast<float4*>(p + o0) = o.a;
        *reinterpret_cast<float4*>(p + o1) = o.b;
        hA = hB;
        hB = hC;
    }
}

extern "C" void kernel_launch(void* const* d_in, const int* in_sizes, int n_in,
                              void* d_out, int out_size) {
    const float* x = (const float*)d_in[0];
    float* out = (float*)d_out;
    const int n_imgs = in_sizes[0] / (EH * EW);     // 16*64 = 1024
    const int total_warps = n_imgs * STRIPS;        // 4096
    const int threads = 256;                        // 8 warps/block
    const int blocks = (total_warps * 32 + threads - 1) / threads;  // 512
    Erosion2d_86517821212128_kernel<<<blocks, threads>>>(x, out, n_imgs);
}

// round 2
// speedup vs baseline: 1.1952x; 1.1952x over previous
#include <cuda_runtime.h>
#include <cuda_bf16.h>

// Erosion2d: out[n,c,y,x] = 3x3 windowed min (pad 1e9) over (16,64,256,256) fp32.
// Separable min: horizontal 3-min via warp shuffles, vertical 3-min via rolling
// register pipeline. One warp per 32-row strip. Each lane holds 8 pixels/row as
// two float4s so all LDG/STG are fully coalesced 512B warp transactions.
//
// R1 changes: regs capped at 64 (__launch_bounds__(256,4)) for 32 warps/SM,
// explicit prefetch-1 pipeline for MLP, STRIPS=8 for grid balance, streaming
// stores to keep L2 clean for strip-boundary read reuse.

#define EH 256
#define EW 256
#define STRIPS 8
#define ROWS_PER_STRIP (EH / STRIPS)

struct Row8 { float4 a, b; };

__device__ __forceinline__ float fmin3(float a, float b, float c) {
    return fminf(a, fminf(b, c));
}

__device__ __forceinline__ Row8 load_row(const float* __restrict__ src, int y,
                                         int o0, int o1) {
    Row8 r;
    if ((unsigned)y < (unsigned)EH) {
        const float* p = src + (size_t)y * EW;
        r.a = *reinterpret_cast<const float4*>(p + o0);
        r.b = *reinterpret_cast<const float4*>(p + o1);
    } else {
        const float inf = __int_as_float(0x7f800000);
        r.a = make_float4(inf, inf, inf, inf);
        r.b = r.a;
    }
    return r;
}

// Horizontal 3-tap min. Lane l holds x = [4l, 4l+4) in .a and
// x = [128+4l, 128+4l+4) in .b. Cross-lane neighbors via shuffle.
__device__ __forceinline__ Row8 hmin_row(Row8 v, int lane) {
    const unsigned FULL = 0xffffffffu;
    const float inf = __int_as_float(0x7f800000);

    float lA   = __shfl_up_sync  (FULL, v.a.w, 1);  // x = 4l-1
    float rA   = __shfl_down_sync(FULL, v.a.x, 1);  // x = 4l+4
    float bx0  = __shfl_sync     (FULL, v.b.x, 0);  // x = 128 (lane 31's rA)
    float aw31 = __shfl_sync     (FULL, v.a.w, 31); // x = 127 (lane 0's lB)
    float lB   = __shfl_up_sync  (FULL, v.b.w, 1);  // x = 128+4l-1
    float rB   = __shfl_down_sync(FULL, v.b.x, 1);  // x = 128+4l+4

    if (lane == 0)  { lA = inf;  lB = aw31; }
    if (lane == 31) { rA = bx0;  rB = inf;  }

    Row8 h;
    h.a.x = fmin3(lA,    v.a.x, v.a.y);
    h.a.y = fmin3(v.a.x, v.a.y, v.a.z);
    h.a.z = fmin3(v.a.y, v.a.z, v.a.w);
    h.a.w = fmin3(v.a.z, v.a.w, rA);
    h.b.x = fmin3(lB,    v.b.x, v.b.y);
    h.b.y = fmin3(v.b.x, v.b.y, v.b.z);
    h.b.z = fmin3(v.b.y, v.b.z, v.b.w);
    h.b.w = fmin3(v.b.z, v.b.w, rB);
    return h;
}

__device__ __forceinline__ Row8 vmin3(Row8 p, Row8 q, Row8 r) {
    Row8 o;
    o.a.x = fmin3(p.a.x, q.a.x, r.a.x);
    o.a.y = fmin3(p.a.y, q.a.y, r.a.y);
    o.a.z = fmin3(p.a.z, q.a.z, r.a.z);
    o.a.w = fmin3(p.a.w, q.a.w, r.a.w);
    o.b.x = fmin3(p.b.x, q.b.x, r.b.x);
    o.b.y = fmin3(p.b.y, q.b.y, r.b.y);
    o.b.z = fmin3(p.b.z, q.b.z, r.b.z);
    o.b.w = fmin3(p.b.w, q.b.w, r.b.w);
    return o;
}

__global__ __launch_bounds__(256, 4)
void Erosion2d_86517821212128_kernel(const float* __restrict__ x,
                                     float* __restrict__ out,
                                     int n_imgs) {
    const int gw    = (int)((blockIdx.x * blockDim.x + threadIdx.x) >> 5);
    const int lane  = (int)(threadIdx.x & 31);
    const int img   = gw >> 3;              // STRIPS = 8
    const int strip = gw & (STRIPS - 1);
    if (img >= n_imgs) return;

    const float* src = x   + (size_t)img * (EH * EW);
    float*       dst = out + (size_t)img * (EH * EW);

    const int o0 = lane * 4;         // x in [0,128)
    const int o1 = 128 + lane * 4;   // x in [128,256)

    const int ys = strip * ROWS_PER_STRIP;

    // Pipeline state: hA = hmin(row y-1), hB = hmin(row y), rN = raw row y+1.
    Row8 hA = hmin_row(load_row(src, ys - 1, o0, o1), lane);
    Row8 hB = hmin_row(load_row(src, ys,     o0, o1), lane);
    Row8 rN = load_row(src, ys + 1, o0, o1);

#pragma unroll 2
    for (int yo = ys; yo < ys + ROWS_PER_STRIP; ++yo) {
        Row8 rP = load_row(src, yo + 2, o0, o1);   // prefetch: in flight during hmin
        Row8 hC = hmin_row(rN, lane);
        Row8 o  = vmin3(hA, hB, hC);
        float* p = dst + (size_t)yo * EW;
        __stcs(reinterpret_cast<float4*>(p + o0), o.a);
        __stcs(reinterpret_cast<float4*>(p + o1), o.b);
        hA = hB;
        hB = hC;
        rN = rP;
    }
}

extern "C" void kernel_launch(void* const* d_in, const int* in_sizes, int n_in,
                              void* d_out, int out_size) {
    const float* x = (const float*)d_in[0];
    float* out = (float*)d_out;
    const int n_imgs = in_sizes[0] / (EH * EW);          // 16*64 = 1024
    const int total_warps = n_imgs * STRIPS;             // 8192
    const int threads = 256;                             // 8 warps/block
    const int blocks = (total_warps * 32 + threads - 1) / threads;  // 1024
    Erosion2d_86517821212128_kernel<<<blocks, threads>>>(x, out, n_imgs);
}